// round 3
// baseline (speedup 1.0000x reference)
#include <cuda_runtime.h>

#define BB 16
#define NN 64
#define CC 32
#define NLVL 4
#define NB 60
#define NE 4096
#define NPAIR (BB*NN*NN)

typedef unsigned long long u64;

__device__ __forceinline__ u64 ffma2(u64 a, u64 b, u64 c) {
    u64 d;
    asm("fma.rn.f32x2 %0, %1, %2, %3;" : "=l"(d) : "l"(a), "l"(b), "l"(c));
    return d;
}
__device__ __forceinline__ u64 packf2(float lo, float hi) {
    u64 r;
    asm("mov.b64 %0, {%1, %2};" : "=l"(r) : "f"(lo), "f"(hi));
    return r;
}
__device__ __forceinline__ float2 unpackf2(u64 v) {
    float2 r;
    asm("mov.b64 {%0, %1}, %2;" : "=f"(r.x), "=f"(r.y) : "l"(v));
    return r;
}

// ---------------- device scratch (static; no allocs) ----------------
__device__ float g_a[2][BB*NN*CC];
__device__ float g_rep[4][BB*NN*7*CC];
__device__ float g_edge[4][NPAIR*CC];
__device__ float g_cut[NPAIR];
__device__ float g_sph[NPAIR*16];
__device__ int   g_e0[NPAIR];
__device__ float g_frac[NPAIR];
__device__ float g_part[BB*NN];
__device__ float g_bas[(NE+1)*NB];
__device__ float2 g_tab2[(NE+1)*512];   // {tab[e], tab[e+1]} per (s,c)

// ---------------- basis table rows ----------------
__global__ void k_bas() {
    int t = blockIdx.x*256 + threadIdx.x;
    if (t >= (NE+1)*NB) return;
    int e = t / NB, k = t - e*NB;
    float r = (float)e * (5.0f/NE);
    float d = r - (float)k * (5.0f/59.0f);
    g_bas[t] = expf(-36.0f * d * d);
}

// ---------------- rad table ----------------
__global__ void __launch_bounds__(256) k_table(const float* __restrict__ W_rad) {
    __shared__ float sW[NB*CC];
    __shared__ float sb[64*NB];
    int s   = blockIdx.y;
    int e0b = blockIdx.x * 64;
    int tid = threadIdx.x;
    const float* wr = W_rad + s*NB*CC;
    for (int idx = tid; idx < NB*CC; idx += 256) sW[idx] = wr[idx];
    int nmax = (NE+1) - e0b; if (nmax > 64) nmax = 64;
    for (int idx = tid; idx < nmax*NB; idx += 256) sb[idx] = g_bas[e0b*NB + idx];
    __syncthreads();
    int c = tid & 31, eg = tid >> 5;
    float acc[8];
    #pragma unroll
    for (int t = 0; t < 8; ++t) acc[t] = 0.0f;
    for (int k = 0; k < NB; ++k) {
        float wv = sW[k*CC + c];
        #pragma unroll
        for (int t = 0; t < 8; ++t)
            acc[t] = fmaf(sb[(eg*8 + t)*NB + k], wv, acc[t]);
    }
    #pragma unroll
    for (int t = 0; t < 8; ++t) {
        int e = e0b + eg*8 + t;
        if (e <= NE) {
            g_tab2[e*512 + s*32 + c].x = acc[t];
            if (e > 0) g_tab2[(e-1)*512 + s*32 + c].y = acc[t];
        }
    }
}

// ---------------- geometry ----------------
__global__ void k_geom(const float* __restrict__ pos) {
    int t = blockIdx.x*256 + threadIdx.x;
    if (t >= NPAIR) return;
    int b = t >> 12, i = (t >> 6) & 63, j = t & 63;
    const float* pi = pos + (b*NN+i)*3;
    const float* pj = pos + (b*NN+j)*3;
    float dx = pi[0]-pj[0], dy = pi[1]-pj[1], dz = pi[2]-pj[2];
    float r = sqrtf(dx*dx + dy*dy + dz*dz + 1e-12f);
    float inv = 1.0f / r;
    float x = dx*inv, y = dy*inv, z = dz*inv;

    float cut = 0.0f;
    if (i != j && r > 1e-4f && r < 5.0f)
        cut = 1.0f / (1.0f + __expf((r - 3.0f) * 2.0f));
    g_cut[t] = cut;

    float fidx = r * ((float)NE / 5.0f);
    int e0 = (int)fidx;
    if (e0 > NE-1) e0 = NE-1;
    float fr = fidx - (float)e0;
    if (fr > 1.0f) fr = 1.0f;
    g_e0[t] = e0;
    g_frac[t] = fr;

    float xx = x*x, yy = y*y, zz = z*z;
    float4 s0 = make_float4(1.0f, x, y, z);
    float4 s1 = make_float4(x*y, y*z, 3.0f*zz - 1.0f, x*z);
    float4 s2 = make_float4(xx - yy, y*(3.0f*xx - yy), x*y*z, y*(5.0f*zz - 1.0f));
    float4 s3 = make_float4(z*(5.0f*zz - 3.0f), x*(5.0f*zz - 1.0f),
                            z*(xx - yy), x*(xx - 3.0f*yy));
    float4* o = (float4*)(g_sph + t*16);
    o[0] = s0; o[1] = s1; o[2] = s2; o[3] = s3;
}

// ---------------- input featurization ----------------
__global__ void k_a0(const float* __restrict__ oh, const int* __restrict__ charges,
                     const float* __restrict__ W_in, const float* __restrict__ b_in) {
    int t = blockIdx.x*256 + threadIdx.x;
    if (t >= BB*NN*CC) return;
    int c = t & 31, n = t >> 5;
    float ch = (float)charges[n] * (1.0f/9.0f);
    float p1 = ch, p2 = ch*ch;
    float acc = b_in[c];
    #pragma unroll
    for (int s = 0; s < 5; ++s) {
        float o = oh[n*5 + s];
        acc += o * (W_in[(s*3+0)*CC + c] + p1*W_in[(s*3+1)*CC + c] + p2*W_in[(s*3+2)*CC + c]);
    }
    g_a[0][t] = acc;
    g_rep[0][(n*7 + 0)*CC + c] = acc;
    if (c == 0) g_part[n] = 0.0f;
}

// ---------------- edge pass for one l (f32x2 GEMM, pipelined loads) ----------------
template<int L, bool HP>
__device__ __forceinline__ void edge_pass(
    const float* sa, const float* sWEl, const float* scut,
    const float* sfrac, const int* se0, const float* ssph,
    float* smsg, float* ge, const float2* tabl, int i, int w, int lane)
{
    const int M = 2*L + 1;
    const int LMB = L*L;

    u64 vreg2[16];
    #pragma unroll
    for (int dp = 0; dp < 16; ++dp) {
        float v0 = sa[i*CC + 2*dp]     * sWEl[(2*dp)*CC + lane];
        float v1 = sa[i*CC + 2*dp + 1] * sWEl[(2*dp+1)*CC + lane];
        vreg2[dp] = packf2(v0, v1);
    }
    float accm[M];
    #pragma unroll
    for (int m = 0; m < M; ++m) accm[m] = 0.0f;

    int j = w;
    float2 tv = tabl[se0[j]*512];
    float gp = HP ? ge[j*CC + lane] : 0.0f;

    #pragma unroll
    for (int jt = 0; jt < 8; ++jt) {
        int jn = j + 8;
        float2 tvn = make_float2(0.0f, 0.0f);
        float gpn = 0.0f;
        if (jt < 7) {
            tvn = tabl[se0[jn]*512];
            if (HP) gpn = ge[jn*CC + lane];
        }
        const ulonglong2* aj = (const ulonglong2*)(sa + j*CC);
        ulonglong2 p0 = aj[0], p1 = aj[1], p2 = aj[2], p3 = aj[3];
        ulonglong2 p4 = aj[4], p5 = aj[5], p6 = aj[6], p7 = aj[7];
        u64 a0 = 0, a1 = 0, a2 = 0, a3 = 0;
        a0 = ffma2(p0.x, vreg2[0],  a0);  a1 = ffma2(p0.y, vreg2[1],  a1);
        a2 = ffma2(p1.x, vreg2[2],  a2);  a3 = ffma2(p1.y, vreg2[3],  a3);
        a0 = ffma2(p2.x, vreg2[4],  a0);  a1 = ffma2(p2.y, vreg2[5],  a1);
        a2 = ffma2(p3.x, vreg2[6],  a2);  a3 = ffma2(p3.y, vreg2[7],  a3);
        a0 = ffma2(p4.x, vreg2[8],  a0);  a1 = ffma2(p4.y, vreg2[9],  a1);
        a2 = ffma2(p5.x, vreg2[10], a2);  a3 = ffma2(p5.y, vreg2[11], a3);
        a0 = ffma2(p6.x, vreg2[12], a0);  a1 = ffma2(p6.y, vreg2[13], a1);
        a2 = ffma2(p7.x, vreg2[14], a2);  a3 = ffma2(p7.y, vreg2[15], a3);
        float2 f0 = unpackf2(a0), f1 = unpackf2(a1);
        float2 f2 = unpackf2(a2), f3 = unpackf2(a3);
        float eacc = ((f0.x + f0.y) + (f1.x + f1.y))
                   + ((f2.x + f2.y) + (f3.x + f3.y)) + gp;
        float rad  = fmaf(sfrac[j], tv.y - tv.x, tv.x);
        float edge = scut[j] * rad * eacc;
        ge[j*CC + lane] = edge;
        const float* sp = ssph + j*16 + LMB;
        #pragma unroll
        for (int m = 0; m < M; ++m)
            accm[m] = fmaf(edge, sp[m], accm[m]);
        tv = tvn; gp = gpn; j = jn;
    }
    #pragma unroll
    for (int m = 0; m < M; ++m)
        smsg[(w*16 + LMB + m)*CC + lane] = accm[m];
}

// ---------------- one full Cormorant level ----------------
__global__ void __launch_bounds__(256) k_level(int lvl,
    const float* __restrict__ W_edge, const float* __restrict__ W_agg,
    const float* __restrict__ W_self, const float* __restrict__ W_top)
{
    __shared__ float sa[NN*CC];          // 8 KB
    __shared__ float scut[NN];
    __shared__ float sfrac[NN];
    __shared__ int   se0[NN];
    __shared__ float ssph[NN*16];        // 4 KB
    __shared__ float sWE[4*CC*CC];       // 16 KB
    __shared__ float smsg[8*16*CC];      // 16 KB
    __shared__ float sred[16*CC];        // 2 KB
    __shared__ float srold[16*CC];       // 2 KB
    __shared__ float srnew[16*CC];       // 2 KB

    const float* acur  = g_a[lvl & 1];
    float*       anext = g_a[(lvl + 1) & 1];

    int blk = blockIdx.x;
    int b = blk >> 6, i = blk & 63;
    int tid = threadIdx.x, w = tid >> 5, lane = tid & 31;
    int pbase = (b*NN + i)*NN;
    int atom  = b*NN + i;

    for (int idx = tid; idx < NN*CC/4; idx += 256)
        ((float4*)sa)[idx] = ((const float4*)(acur + b*NN*CC))[idx];
    for (int idx = tid; idx < NN/4; idx += 256) {
        ((float4*)scut)[idx]  = ((const float4*)(g_cut  + pbase))[idx];
        ((float4*)sfrac)[idx] = ((const float4*)(g_frac + pbase))[idx];
        ((int4*)se0)[idx]     = ((const int4*)  (g_e0   + pbase))[idx];
    }
    for (int idx = tid; idx < NN*16/4; idx += 256)
        ((float4*)ssph)[idx] = ((const float4*)(g_sph + pbase*16))[idx];
    {
        const float4* wsrc = (const float4*)(W_edge + lvl*4*CC*CC);
        for (int idx = tid; idx < CC*CC; idx += 256)   // 1024 float4
            ((float4*)sWE)[idx] = wsrc[idx];
    }
    for (int o = tid; o < 512; o += 256) {
        int lm = o >> 5, c = o & 31;
        int l = (lm == 0) ? 0 : (lm < 4) ? 1 : (lm < 9) ? 2 : 3;
        int m = lm - l*l;
        bool hs = (lvl > 0) || (lm == 0);
        srold[o] = hs ? g_rep[l][(atom*7 + m)*CC + c] : 0.0f;
    }
    __syncthreads();

    {
        const float2* tab0 = g_tab2 + (lvl*4)*32 + lane;
        if (lvl == 0) {
            edge_pass<0,false>(sa, sWE + 0*1024, scut, sfrac, se0, ssph, smsg, g_edge[0] + pbase*CC, tab0 +  0, i, w, lane);
            edge_pass<1,false>(sa, sWE + 1*1024, scut, sfrac, se0, ssph, smsg, g_edge[1] + pbase*CC, tab0 + 32, i, w, lane);
            edge_pass<2,false>(sa, sWE + 2*1024, scut, sfrac, se0, ssph, smsg, g_edge[2] + pbase*CC, tab0 + 64, i, w, lane);
            edge_pass<3,false>(sa, sWE + 3*1024, scut, sfrac, se0, ssph, smsg, g_edge[3] + pbase*CC, tab0 + 96, i, w, lane);
        } else {
            edge_pass<0,true >(sa, sWE + 0*1024, scut, sfrac, se0, ssph, smsg, g_edge[0] + pbase*CC, tab0 +  0, i, w, lane);
            edge_pass<1,true >(sa, sWE + 1*1024, scut, sfrac, se0, ssph, smsg, g_edge[1] + pbase*CC, tab0 + 32, i, w, lane);
            edge_pass<2,true >(sa, sWE + 2*1024, scut, sfrac, se0, ssph, smsg, g_edge[2] + pbase*CC, tab0 + 64, i, w, lane);
            edge_pass<3,true >(sa, sWE + 3*1024, scut, sfrac, se0, ssph, smsg, g_edge[3] + pbase*CC, tab0 + 96, i, w, lane);
        }
    }
    __syncthreads();

    // warp reduction of messages
    for (int o = tid; o < 512; o += 256) {
        float s = 0.0f;
        #pragma unroll
        for (int ww = 0; ww < 8; ++ww) s += smsg[(ww*16)*CC + o];
        sred[o] = s;
    }
    __syncthreads();

    // atom-level GEMM (agg + self) for all 16 (l,m) rows
    for (int o = tid; o < 512; o += 256) {
        int lm = o >> 5, d = o & 31;
        int l = (lm == 0) ? 0 : (lm < 4) ? 1 : (lm < 9) ? 2 : 3;
        int m = lm - l*l;
        const float* wa  = W_agg  + (lvl*4 + l)*CC*CC;
        const float* wsf = W_self + (lvl*4 + l)*CC*CC;
        float r = 0.0f, r2 = 0.0f;
        #pragma unroll
        for (int c2 = 0; c2 < CC; ++c2) {
            r  = fmaf(sred [lm*CC + c2], wa [c2*CC + d], r);
            r2 = fmaf(srold[lm*CC + c2], wsf[c2*CC + d], r2);
        }
        r += r2;
        srnew[o] = r;
        g_rep[l][(atom*7 + m)*CC + d] = r;
        if (lm == 0) anext[atom*CC + d] = r;
    }
    __syncthreads();

    // features + head contribution
    float part = 0.0f;
    if (tid < 128) {
        int l = tid >> 5, c = tid & 31;
        float f;
        if (l == 0) {
            f = srnew[c];
        } else {
            float s2 = 0.0f;
            #pragma unroll
            for (int m = 0; m < 7; ++m)
                if (m < 2*l + 1) { float v = srnew[(l*l + m)*CC + c]; s2 += v*v; }
            f = sqrtf(s2 + 1e-12f);
        }
        part = f * W_top[(lvl*4 + l)*CC + c];
    }
    #pragma unroll
    for (int off = 16; off; off >>= 1)
        part += __shfl_down_sync(0xffffffffu, part, off);
    __syncthreads();
    if (lane == 0) sred[w] = part;
    __syncthreads();
    if (tid == 0) {
        float s = 0.0f;
        #pragma unroll
        for (int ww = 0; ww < 8; ++ww) s += sred[ww];
        g_part[atom] += s;
    }
}

// ---------------- output ----------------
__global__ void k_out(float* __restrict__ out, const float* __restrict__ b_top) {
    __shared__ float s[64];
    int b = blockIdx.x, t = threadIdx.x;
    s[t] = g_part[b*NN + t];
    __syncthreads();
    #pragma unroll
    for (int off = 32; off; off >>= 1) {
        if (t < off) s[t] += s[t + off];
        __syncthreads();
    }
    if (t == 0) out[b] = s[0] + b_top[0];
}

// ---------------- launch ----------------
extern "C" void kernel_launch(void* const* d_in, const int* in_sizes, int n_in,
                              void* d_out, int out_size) {
    const float* pos     = (const float*)d_in[0];
    const float* oh      = (const float*)d_in[1];
    const int*   charges = (const int*)  d_in[2];
    const float* W_in    = (const float*)d_in[5];
    const float* b_in    = (const float*)d_in[6];
    const float* W_rad   = (const float*)d_in[7];
    const float* W_edge  = (const float*)d_in[8];
    const float* W_agg   = (const float*)d_in[9];
    const float* W_self  = (const float*)d_in[10];
    const float* W_top   = (const float*)d_in[11];
    const float* b_top   = (const float*)d_in[12];

    k_bas<<<((NE+1)*NB + 255)/256, 256>>>();
    k_table<<<dim3((NE+64)/64, 16), 256>>>(W_rad);
    k_geom<<<NPAIR/256, 256>>>(pos);
    k_a0<<<(BB*NN*CC)/256, 256>>>(oh, charges, W_in, b_in);
    for (int lvl = 0; lvl < NLVL; ++lvl)
        k_level<<<BB*NN, 256>>>(lvl, W_edge, W_agg, W_self, W_top);
    k_out<<<BB, 64>>>((float*)d_out, b_top);
}

// round 4
// speedup vs baseline: 1.8942x; 1.8942x over previous
#include <cuda_runtime.h>

#define BB 16
#define NN 64
#define CC 32
#define NLVL 4
#define NB 60
#define NE 4096
#define NPAIR (BB*NN*NN)

// ---------------- device scratch (static; no allocs) ----------------
__device__ float g_a[2][BB*NN*CC];
__device__ float g_rep[4][BB*NN*7*CC];
__device__ float g_edge[4][NPAIR*CC];
__device__ float g_cut[NPAIR];
__device__ float g_sph[NPAIR*16];
__device__ int   g_e0[NPAIR];
__device__ float g_frac[NPAIR];
__device__ float g_part4[BB*NN*4];      // per (atom, l) head partials
__device__ float g_bas[(NE+1)*NB];
__device__ float2 g_tab2[(NE+1)*512];   // {tab[e], tab[e+1]} per (s,c)

// ---------------- basis table rows ----------------
__global__ void k_bas() {
    int t = blockIdx.x*256 + threadIdx.x;
    if (t >= (NE+1)*NB) return;
    int e = t / NB, k = t - e*NB;
    float r = (float)e * (5.0f/NE);
    float d = r - (float)k * (5.0f/59.0f);
    g_bas[t] = expf(-36.0f * d * d);
}

// ---------------- rad table ----------------
__global__ void __launch_bounds__(256) k_table(const float* __restrict__ W_rad) {
    __shared__ float sW[NB*CC];
    __shared__ float sb[64*NB];
    int s   = blockIdx.y;
    int e0b = blockIdx.x * 64;
    int tid = threadIdx.x;
    const float* wr = W_rad + s*NB*CC;
    for (int idx = tid; idx < NB*CC; idx += 256) sW[idx] = wr[idx];
    int nmax = (NE+1) - e0b; if (nmax > 64) nmax = 64;
    for (int idx = tid; idx < nmax*NB; idx += 256) sb[idx] = g_bas[e0b*NB + idx];
    __syncthreads();
    int c = tid & 31, eg = tid >> 5;
    float acc[8];
    #pragma unroll
    for (int t = 0; t < 8; ++t) acc[t] = 0.0f;
    for (int k = 0; k < NB; ++k) {
        float wv = sW[k*CC + c];
        #pragma unroll
        for (int t = 0; t < 8; ++t)
            acc[t] = fmaf(sb[(eg*8 + t)*NB + k], wv, acc[t]);
    }
    #pragma unroll
    for (int t = 0; t < 8; ++t) {
        int e = e0b + eg*8 + t;
        if (e <= NE) {
            g_tab2[e*512 + s*32 + c].x = acc[t];
            if (e > 0) g_tab2[(e-1)*512 + s*32 + c].y = acc[t];
        }
    }
}

// ---------------- geometry ----------------
__global__ void k_geom(const float* __restrict__ pos) {
    int t = blockIdx.x*256 + threadIdx.x;
    if (t >= NPAIR) return;
    int b = t >> 12, i = (t >> 6) & 63, j = t & 63;
    const float* pi = pos + (b*NN+i)*3;
    const float* pj = pos + (b*NN+j)*3;
    float dx = pi[0]-pj[0], dy = pi[1]-pj[1], dz = pi[2]-pj[2];
    float r = sqrtf(dx*dx + dy*dy + dz*dz + 1e-12f);
    float inv = 1.0f / r;
    float x = dx*inv, y = dy*inv, z = dz*inv;

    float cut = 0.0f;
    if (i != j && r > 1e-4f && r < 5.0f)
        cut = 1.0f / (1.0f + __expf((r - 3.0f) * 2.0f));
    g_cut[t] = cut;

    float fidx = r * ((float)NE / 5.0f);
    int e0 = (int)fidx;
    if (e0 > NE-1) e0 = NE-1;
    float fr = fidx - (float)e0;
    if (fr > 1.0f) fr = 1.0f;
    g_e0[t] = e0;
    g_frac[t] = fr;

    float xx = x*x, yy = y*y, zz = z*z;
    float4 s0 = make_float4(1.0f, x, y, z);
    float4 s1 = make_float4(x*y, y*z, 3.0f*zz - 1.0f, x*z);
    float4 s2 = make_float4(xx - yy, y*(3.0f*xx - yy), x*y*z, y*(5.0f*zz - 1.0f));
    float4 s3 = make_float4(z*(5.0f*zz - 3.0f), x*(5.0f*zz - 1.0f),
                            z*(xx - yy), x*(xx - 3.0f*yy));
    float4* o = (float4*)(g_sph + t*16);
    o[0] = s0; o[1] = s1; o[2] = s2; o[3] = s3;
}

// ---------------- input featurization ----------------
__global__ void k_a0(const float* __restrict__ oh, const int* __restrict__ charges,
                     const float* __restrict__ W_in, const float* __restrict__ b_in) {
    int t = blockIdx.x*256 + threadIdx.x;
    if (t >= BB*NN*CC) return;
    int c = t & 31, n = t >> 5;
    float ch = (float)charges[n] * (1.0f/9.0f);
    float p1 = ch, p2 = ch*ch;
    float acc = b_in[c];
    #pragma unroll
    for (int s = 0; s < 5; ++s) {
        float o = oh[n*5 + s];
        acc += o * (W_in[(s*3+0)*CC + c] + p1*W_in[(s*3+1)*CC + c] + p2*W_in[(s*3+2)*CC + c]);
    }
    g_a[0][t] = acc;
    g_rep[0][(n*7 + 0)*CC + c] = acc;
    if (t < BB*NN*4) g_part4[t] = 0.0f;
}

// ---------------- per-l edge + message pass (R2-style scalar FFMA) ----------------
template<int L, bool HP>
__device__ __forceinline__ void jloop(
    const float* sa, const float* sWE, const float* scut,
    const float* sfrac, const int* se0, const float* ssph,
    float* smsg, float* ge, const float2* tabl, int i, int w, int lane)
{
    const int M = 2*L + 1;
    float vreg[32];
    #pragma unroll
    for (int d = 0; d < 32; ++d)
        vreg[d] = sa[i*CC + d] * sWE[d*CC + lane];

    float accm[M];
    #pragma unroll
    for (int m = 0; m < M; ++m) accm[m] = 0.0f;

    int j = w;
    float2 tv = tabl[se0[j]*512];
    float gp = HP ? ge[j*CC + lane] : 0.0f;

    #pragma unroll
    for (int jt = 0; jt < 8; ++jt) {
        int jn = j + 8;
        float2 tvn = make_float2(0.0f, 0.0f);
        float gpn = 0.0f;
        if (jt < 7) {
            tvn = tabl[se0[jn]*512];
            if (HP) gpn = ge[jn*CC + lane];
        }
        const float4* aj4 = (const float4*)(sa + j*CC);
        float ea0 = 0.f, ea1 = 0.f, ea2 = 0.f, ea3 = 0.f;
        #pragma unroll
        for (int q = 0; q < 8; ++q) {
            float4 s4 = aj4[q];
            ea0 = fmaf(s4.x, vreg[4*q+0], ea0);
            ea1 = fmaf(s4.y, vreg[4*q+1], ea1);
            ea2 = fmaf(s4.z, vreg[4*q+2], ea2);
            ea3 = fmaf(s4.w, vreg[4*q+3], ea3);
        }
        float eacc = (ea0 + ea1) + (ea2 + ea3) + gp;
        float rad  = fmaf(sfrac[j], tv.y - tv.x, tv.x);
        float edge = scut[j] * rad * eacc;
        ge[j*CC + lane] = edge;
        const float* sp = ssph + j*8;
        #pragma unroll
        for (int m = 0; m < M; ++m)
            accm[m] = fmaf(edge, sp[m], accm[m]);
        tv = tvn; gp = gpn; j = jn;
    }
    #pragma unroll
    for (int m = 0; m < M; ++m)
        smsg[(w*7 + m)*CC + lane] = accm[m];
}

// ---------------- one (b, i, l) block ----------------
__global__ void __launch_bounds__(256) k_level(int lvl,
    const float* __restrict__ W_edge, const float* __restrict__ W_agg,
    const float* __restrict__ W_self, const float* __restrict__ W_top)
{
    __shared__ float sa[NN*CC];        // 8 KB
    __shared__ float scut[NN];
    __shared__ float sfrac[NN];
    __shared__ int   se0[NN];
    __shared__ float ssph[NN*8];       // 2 KB (this l's components, padded)
    __shared__ float sWE[CC*CC];       // 4 KB
    __shared__ float smsg[8*7*CC];     // 7 KB
    __shared__ float sred[7*CC];
    __shared__ float srold[7*CC];
    __shared__ float srnew[7*CC];

    const float* acur  = g_a[lvl & 1];
    float*       anext = g_a[(lvl + 1) & 1];

    int blk = blockIdx.x;
    int l = blk & 3;
    int atom = blk >> 2;
    int b = atom >> 6, i = atom & 63;
    const int M = 2*l + 1;
    int tid = threadIdx.x, w = tid >> 5, lane = tid & 31;
    int pbase = atom*NN;
    int s = lvl*4 + l;

    for (int idx = tid; idx < NN*CC/4; idx += 256)
        ((float4*)sa)[idx] = ((const float4*)(acur + b*NN*CC))[idx];
    for (int idx = tid; idx < NN/4; idx += 256) {
        ((float4*)scut)[idx]  = ((const float4*)(g_cut  + pbase))[idx];
        ((float4*)sfrac)[idx] = ((const float4*)(g_frac + pbase))[idx];
        ((int4*)se0)[idx]     = ((const int4*)  (g_e0   + pbase))[idx];
    }
    for (int t = tid; t < NN*8; t += 256) {
        int j = t >> 3, m = t & 7;
        ssph[t] = (m < M) ? g_sph[(pbase + j)*16 + l*l + m] : 0.0f;
    }
    {
        const float4* wsrc = (const float4*)(W_edge + s*CC*CC);
        for (int idx = tid; idx < CC*CC/4; idx += 256)
            ((float4*)sWE)[idx] = wsrc[idx];
    }
    bool has_self = (lvl > 0) || (l == 0);
    if (tid < M*CC)
        srold[tid] = has_self ? g_rep[l][atom*7*CC + tid] : 0.0f;
    __syncthreads();

    {
        float* ge = g_edge[l] + pbase*CC;
        const float2* tabl = g_tab2 + s*32 + lane;
        if (lvl == 0) {
            switch (l) {
                case 0: jloop<0,false>(sa, sWE, scut, sfrac, se0, ssph, smsg, ge, tabl, i, w, lane); break;
                case 1: jloop<1,false>(sa, sWE, scut, sfrac, se0, ssph, smsg, ge, tabl, i, w, lane); break;
                case 2: jloop<2,false>(sa, sWE, scut, sfrac, se0, ssph, smsg, ge, tabl, i, w, lane); break;
                default:jloop<3,false>(sa, sWE, scut, sfrac, se0, ssph, smsg, ge, tabl, i, w, lane); break;
            }
        } else {
            switch (l) {
                case 0: jloop<0,true >(sa, sWE, scut, sfrac, se0, ssph, smsg, ge, tabl, i, w, lane); break;
                case 1: jloop<1,true >(sa, sWE, scut, sfrac, se0, ssph, smsg, ge, tabl, i, w, lane); break;
                case 2: jloop<2,true >(sa, sWE, scut, sfrac, se0, ssph, smsg, ge, tabl, i, w, lane); break;
                default:jloop<3,true >(sa, sWE, scut, sfrac, se0, ssph, smsg, ge, tabl, i, w, lane); break;
            }
        }
    }
    __syncthreads();

    if (tid < M*CC) {
        float sm = 0.0f;
        #pragma unroll
        for (int ww = 0; ww < 8; ++ww) sm += smsg[ww*7*CC + tid];
        sred[tid] = sm;
    }
    __syncthreads();

    if (tid < M*CC) {
        int m = tid >> 5, d = tid & 31;
        const float* wa  = W_agg  + s*CC*CC;
        const float* wsf = W_self + s*CC*CC;
        float r = 0.0f, r2 = 0.0f;
        #pragma unroll
        for (int c2 = 0; c2 < CC; ++c2) {
            r  = fmaf(sred [m*CC + c2], wa [c2*CC + d], r);
            r2 = fmaf(srold[m*CC + c2], wsf[c2*CC + d], r2);
        }
        r += r2;
        srnew[tid] = r;
        g_rep[l][(atom*7 + m)*CC + d] = r;
        if (m == 0 && l == 0) anext[atom*CC + d] = r;
    }
    __syncthreads();

    if (tid < 32) {
        float f;
        if (l == 0) {
            f = srnew[tid];
        } else {
            float s2 = 0.0f;
            #pragma unroll
            for (int m = 0; m < 7; ++m)
                if (m < M) { float v = srnew[m*CC + tid]; s2 += v*v; }
            f = sqrtf(s2 + 1e-12f);
        }
        float part = f * W_top[s*CC + tid];
        #pragma unroll
        for (int off = 16; off; off >>= 1)
            part += __shfl_down_sync(0xffffffffu, part, off);
        if (tid == 0) g_part4[atom*4 + l] += part;
    }
}

// ---------------- output ----------------
__global__ void k_out(float* __restrict__ out, const float* __restrict__ b_top) {
    __shared__ float sh[256];
    int b = blockIdx.x, t = threadIdx.x;
    sh[t] = g_part4[b*256 + t];
    __syncthreads();
    #pragma unroll
    for (int off = 128; off; off >>= 1) {
        if (t < off) sh[t] += sh[t + off];
        __syncthreads();
    }
    if (t == 0) out[b] = sh[0] + b_top[0];
}

// ---------------- launch ----------------
extern "C" void kernel_launch(void* const* d_in, const int* in_sizes, int n_in,
                              void* d_out, int out_size) {
    const float* pos     = (const float*)d_in[0];
    const float* oh      = (const float*)d_in[1];
    const int*   charges = (const int*)  d_in[2];
    const float* W_in    = (const float*)d_in[5];
    const float* b_in    = (const float*)d_in[6];
    const float* W_rad   = (const float*)d_in[7];
    const float* W_edge  = (const float*)d_in[8];
    const float* W_agg   = (const float*)d_in[9];
    const float* W_self  = (const float*)d_in[10];
    const float* W_top   = (const float*)d_in[11];
    const float* b_top   = (const float*)d_in[12];

    k_bas<<<((NE+1)*NB + 255)/256, 256>>>();
    k_table<<<dim3((NE+64)/64, 16), 256>>>(W_rad);
    k_geom<<<NPAIR/256, 256>>>(pos);
    k_a0<<<(BB*NN*CC)/256, 256>>>(oh, charges, W_in, b_in);
    for (int lvl = 0; lvl < NLVL; ++lvl)
        k_level<<<BB*NN*4, 256>>>(lvl, W_edge, W_agg, W_self, W_top);
    k_out<<<BB, 256>>>((float*)d_out, b_top);
}

// round 5
// speedup vs baseline: 2.3874x; 1.2604x over previous
#include <cuda_runtime.h>

#define BB 16
#define NN 64
#define CC 32
#define NLVL 4
#define NB 60
#define NE 4096
#define NPAIR (BB*NN*NN)

// ---------------- device scratch (static; no allocs) ----------------
__device__ float g_a[2][BB*NN*CC];
__device__ float g_rep[4][BB*NN*7*CC];
__device__ float g_edge[4][NPAIR*CC];
__device__ float g_cut[NPAIR];
__device__ float g_sph[NPAIR*16];
__device__ int   g_e0[NPAIR];
__device__ float g_frac[NPAIR];
__device__ float g_part4[BB*NN*4];
__device__ float g_bas[(NE+1)*NB];
__device__ float2 g_tab2[(NE+1)*512];

// ---------------- basis table rows ----------------
__global__ void k_bas() {
    int t = blockIdx.x*256 + threadIdx.x;
    if (t >= (NE+1)*NB) return;
    int e = t / NB, k = t - e*NB;
    float r = (float)e * (5.0f/NE);
    float d = r - (float)k * (5.0f/59.0f);
    g_bas[t] = expf(-36.0f * d * d);
}

// ---------------- rad table ----------------
__global__ void __launch_bounds__(256) k_table(const float* __restrict__ W_rad) {
    __shared__ float sW[NB*CC];
    __shared__ float sb[64*NB];
    int s   = blockIdx.y;
    int e0b = blockIdx.x * 64;
    int tid = threadIdx.x;
    const float* wr = W_rad + s*NB*CC;
    for (int idx = tid; idx < NB*CC; idx += 256) sW[idx] = wr[idx];
    int nmax = (NE+1) - e0b; if (nmax > 64) nmax = 64;
    for (int idx = tid; idx < nmax*NB; idx += 256) sb[idx] = g_bas[e0b*NB + idx];
    __syncthreads();
    int c = tid & 31, eg = tid >> 5;
    float acc[8];
    #pragma unroll
    for (int t = 0; t < 8; ++t) acc[t] = 0.0f;
    for (int k = 0; k < NB; ++k) {
        float wv = sW[k*CC + c];
        #pragma unroll
        for (int t = 0; t < 8; ++t)
            acc[t] = fmaf(sb[(eg*8 + t)*NB + k], wv, acc[t]);
    }
    #pragma unroll
    for (int t = 0; t < 8; ++t) {
        int e = e0b + eg*8 + t;
        if (e <= NE) {
            g_tab2[e*512 + s*32 + c].x = acc[t];
            if (e > 0) g_tab2[(e-1)*512 + s*32 + c].y = acc[t];
        }
    }
}

// ---------------- geometry ----------------
__global__ void k_geom(const float* __restrict__ pos) {
    int t = blockIdx.x*256 + threadIdx.x;
    if (t >= NPAIR) return;
    int b = t >> 12, i = (t >> 6) & 63, j = t & 63;
    const float* pi = pos + (b*NN+i)*3;
    const float* pj = pos + (b*NN+j)*3;
    float dx = pi[0]-pj[0], dy = pi[1]-pj[1], dz = pi[2]-pj[2];
    float r = sqrtf(dx*dx + dy*dy + dz*dz + 1e-12f);
    float inv = 1.0f / r;
    float x = dx*inv, y = dy*inv, z = dz*inv;

    float cut = 0.0f;
    if (i != j && r > 1e-4f && r < 5.0f)
        cut = 1.0f / (1.0f + __expf((r - 3.0f) * 2.0f));
    g_cut[t] = cut;

    float fidx = r * ((float)NE / 5.0f);
    int e0 = (int)fidx;
    if (e0 > NE-1) e0 = NE-1;
    float fr = fidx - (float)e0;
    if (fr > 1.0f) fr = 1.0f;
    g_e0[t] = e0;
    g_frac[t] = fr;

    float xx = x*x, yy = y*y, zz = z*z;
    float4 s0 = make_float4(1.0f, x, y, z);
    float4 s1 = make_float4(x*y, y*z, 3.0f*zz - 1.0f, x*z);
    float4 s2 = make_float4(xx - yy, y*(3.0f*xx - yy), x*y*z, y*(5.0f*zz - 1.0f));
    float4 s3 = make_float4(z*(5.0f*zz - 3.0f), x*(5.0f*zz - 1.0f),
                            z*(xx - yy), x*(xx - 3.0f*yy));
    float4* o = (float4*)(g_sph + t*16);
    o[0] = s0; o[1] = s1; o[2] = s2; o[3] = s3;
}

// ---------------- input featurization ----------------
__global__ void k_a0(const float* __restrict__ oh, const int* __restrict__ charges,
                     const float* __restrict__ W_in, const float* __restrict__ b_in) {
    int t = blockIdx.x*256 + threadIdx.x;
    if (t >= BB*NN*CC) return;
    int c = t & 31, n = t >> 5;
    float ch = (float)charges[n] * (1.0f/9.0f);
    float p1 = ch, p2 = ch*ch;
    float acc = b_in[c];
    #pragma unroll
    for (int s = 0; s < 5; ++s) {
        float o = oh[n*5 + s];
        acc += o * (W_in[(s*3+0)*CC + c] + p1*W_in[(s*3+1)*CC + c] + p2*W_in[(s*3+2)*CC + c]);
    }
    g_a[0][t] = acc;
    g_rep[0][(n*7 + 0)*CC + c] = acc;
    if (t < BB*NN*4) g_part4[t] = 0.0f;
}

// ---------------- per-warp full work for one (atom, l) ----------------
template<int L, bool HP>
__device__ __forceinline__ void atom_warp(
    const float* sa, const float* sWE, const float2* cf,
    const int* e0p, float* sphw,           // warp-private smem slice (512 floats)
    float* ge, const float2* tabl, int i_local, int atom, int lane, int lvl, int s,
    const float* W_agg, const float* W_self, const float* W_top,
    float* anext)
{
    const int M = 2*L + 1;

    float vreg[32];
    #pragma unroll
    for (int d = 0; d < 32; ++d)
        vreg[d] = sa[i_local*CC + d] * sWE[d*CC + lane];

    float accm[M];
    #pragma unroll
    for (int m = 0; m < M; ++m) accm[m] = 0.0f;

    // depth-2 pipeline on table + previous-edge loads
    float2 tv0 = tabl[e0p[0]*512];
    float2 tv1 = tabl[e0p[1]*512];
    float gp0 = HP ? ge[lane]        : 0.0f;
    float gp1 = HP ? ge[CC + lane]   : 0.0f;

    #pragma unroll 4
    for (int jt = 0; jt < 64; ++jt) {
        int jn = jt + 2; if (jn > 63) jn = 63;
        float2 tvn = tabl[e0p[jn]*512];
        float gpn = HP ? ge[jn*CC + lane] : 0.0f;

        const float4* aj4 = (const float4*)(sa + jt*CC);
        float ea0 = 0.f, ea1 = 0.f, ea2 = 0.f, ea3 = 0.f;
        #pragma unroll
        for (int q = 0; q < 8; ++q) {
            float4 s4 = aj4[q];
            ea0 = fmaf(s4.x, vreg[4*q+0], ea0);
            ea1 = fmaf(s4.y, vreg[4*q+1], ea1);
            ea2 = fmaf(s4.z, vreg[4*q+2], ea2);
            ea3 = fmaf(s4.w, vreg[4*q+3], ea3);
        }
        float eacc = (ea0 + ea1) + (ea2 + ea3) + gp0;
        float2 c2 = cf[jt];
        float rad  = fmaf(c2.y, tv0.y - tv0.x, tv0.x);
        float edge = c2.x * rad * eacc;
        ge[jt*CC + lane] = edge;
        const float* sp = sphw + jt*8;
        #pragma unroll
        for (int m = 0; m < M; ++m)
            accm[m] = fmaf(edge, sp[m], accm[m]);

        tv0 = tv1; tv1 = tvn;
        gp0 = gp1; gp1 = gpn;
    }

    // ---- per-warp epilogue (reuse warp's sph slice) ----
    __syncwarp();
    float* wmsg = sphw;          // M*32 <= 224
    float* sold = sphw + 256;    // M*32 <= 224
    bool has_self = (lvl > 0) || (L == 0);
    #pragma unroll
    for (int m = 0; m < M; ++m) {
        wmsg[m*32 + lane] = accm[m];
        sold[m*32 + lane] = has_self ? g_rep[L][(atom*7 + m)*CC + lane] : 0.0f;
    }
    __syncwarp();

    const float* wa  = W_agg  + s*CC*CC;
    const float* wsf = W_self + s*CC*CC;
    float f;
    float s2 = 0.0f;
    float rep0 = 0.0f;
    #pragma unroll
    for (int m = 0; m < M; ++m) {
        float r = 0.0f, r2 = 0.0f;
        #pragma unroll
        for (int c = 0; c < CC; ++c) {
            r  = fmaf(wmsg[m*32 + c], wa [c*CC + lane], r);
            r2 = fmaf(sold[m*32 + c], wsf[c*CC + lane], r2);
        }
        r += r2;
        g_rep[L][(atom*7 + m)*CC + lane] = r;
        if (m == 0) rep0 = r;
        s2 = fmaf(r, r, s2);
    }
    if (L == 0) {
        anext[atom*CC + lane] = rep0;
        f = rep0;
    } else {
        f = sqrtf(s2 + 1e-12f);
    }
    float part = f * W_top[s*CC + lane];
    #pragma unroll
    for (int off = 16; off; off >>= 1)
        part += __shfl_down_sync(0xffffffffu, part, off);
    if (lane == 0) g_part4[atom*4 + L] += part;
}

// ---------------- one (b, atom-group, l) block; warp = one atom ----------------
__global__ void __launch_bounds__(256) k_level(int lvl,
    const float* __restrict__ W_edge, const float* __restrict__ W_agg,
    const float* __restrict__ W_self, const float* __restrict__ W_top)
{
    __shared__ float  sa[NN*CC];        // 8 KB
    __shared__ float  sWE[CC*CC];       // 4 KB
    __shared__ float2 scf[8*NN];        // 4 KB (cut, frac) for 8 atoms
    __shared__ int    se0[8*NN];        // 2 KB
    __shared__ float  ssph[8*NN*8];     // 16 KB; per-warp slice reused in epilogue

    const float* acur  = g_a[lvl & 1];
    float*       anext = g_a[(lvl + 1) & 1];

    int blk = blockIdx.x;
    int l  = blk & 3;
    int bg = blk >> 2;               // b*8 + ig
    int b  = bg >> 3;
    const int M = 2*l + 1;
    int tid = threadIdx.x, w = tid >> 5, lane = tid & 31;
    int atom0 = bg*8;                // global index of first atom in group
    int s = lvl*4 + l;

    // prologue
    for (int idx = tid; idx < NN*CC/4; idx += 256)
        ((float4*)sa)[idx] = ((const float4*)(acur + b*NN*CC))[idx];
    {
        const float4* wsrc = (const float4*)(W_edge + s*CC*CC);
        for (int idx = tid; idx < CC*CC/4; idx += 256)
            ((float4*)sWE)[idx] = wsrc[idx];
    }
    for (int t = tid; t < 512; t += 256) {
        scf[t] = make_float2(g_cut[atom0*NN + t], g_frac[atom0*NN + t]);
        se0[t] = g_e0[atom0*NN + t];
    }
    for (int t = tid; t < 8*NN*8; t += 256) {
        int wi = t >> 9, rem = t & 511, j = rem >> 3, m = rem & 7;
        ssph[t] = (m < M) ? g_sph[((atom0 + wi)*NN + j)*16 + l*l + m] : 0.0f;
    }
    __syncthreads();

    int atom = atom0 + w;
    int i_local = atom & 63;
    float* ge = g_edge[l] + atom*NN*CC;
    const float2* tabl = g_tab2 + s*32 + lane;
    const float2* cf = scf + w*NN;
    const int* e0p = se0 + w*NN;
    float* sphw = ssph + w*512;

    if (lvl == 0) {
        switch (l) {
            case 0: atom_warp<0,false>(sa,sWE,cf,e0p,sphw,ge,tabl,i_local,atom,lane,lvl,s,W_agg,W_self,W_top,anext); break;
            case 1: atom_warp<1,false>(sa,sWE,cf,e0p,sphw,ge,tabl,i_local,atom,lane,lvl,s,W_agg,W_self,W_top,anext); break;
            case 2: atom_warp<2,false>(sa,sWE,cf,e0p,sphw,ge,tabl,i_local,atom,lane,lvl,s,W_agg,W_self,W_top,anext); break;
            default:atom_warp<3,false>(sa,sWE,cf,e0p,sphw,ge,tabl,i_local,atom,lane,lvl,s,W_agg,W_self,W_top,anext); break;
        }
    } else {
        switch (l) {
            case 0: atom_warp<0,true >(sa,sWE,cf,e0p,sphw,ge,tabl,i_local,atom,lane,lvl,s,W_agg,W_self,W_top,anext); break;
            case 1: atom_warp<1,true >(sa,sWE,cf,e0p,sphw,ge,tabl,i_local,atom,lane,lvl,s,W_agg,W_self,W_top,anext); break;
            case 2: atom_warp<2,true >(sa,sWE,cf,e0p,sphw,ge,tabl,i_local,atom,lane,lvl,s,W_agg,W_self,W_top,anext); break;
            default:atom_warp<3,true >(sa,sWE,cf,e0p,sphw,ge,tabl,i_local,atom,lane,lvl,s,W_agg,W_self,W_top,anext); break;
        }
    }
}

// ---------------- output ----------------
__global__ void k_out(float* __restrict__ out, const float* __restrict__ b_top) {
    __shared__ float sh[256];
    int b = blockIdx.x, t = threadIdx.x;
    sh[t] = g_part4[b*256 + t];
    __syncthreads();
    #pragma unroll
    for (int off = 128; off; off >>= 1) {
        if (t < off) sh[t] += sh[t + off];
        __syncthreads();
    }
    if (t == 0) out[b] = sh[0] + b_top[0];
}

// ---------------- launch ----------------
extern "C" void kernel_launch(void* const* d_in, const int* in_sizes, int n_in,
                              void* d_out, int out_size) {
    const float* pos     = (const float*)d_in[0];
    const float* oh      = (const float*)d_in[1];
    const int*   charges = (const int*)  d_in[2];
    const float* W_in    = (const float*)d_in[5];
    const float* b_in    = (const float*)d_in[6];
    const float* W_rad   = (const float*)d_in[7];
    const float* W_edge  = (const float*)d_in[8];
    const float* W_agg   = (const float*)d_in[9];
    const float* W_self  = (const float*)d_in[10];
    const float* W_top   = (const float*)d_in[11];
    const float* b_top   = (const float*)d_in[12];

    k_bas<<<((NE+1)*NB + 255)/256, 256>>>();
    k_table<<<dim3((NE+64)/64, 16), 256>>>(W_rad);
    k_geom<<<NPAIR/256, 256>>>(pos);
    k_a0<<<(BB*NN*CC)/256, 256>>>(oh, charges, W_in, b_in);
    for (int lvl = 0; lvl < NLVL; ++lvl)
        k_level<<<BB*8*4, 256>>>(lvl, W_edge, W_agg, W_self, W_top);
    k_out<<<BB, 256>>>((float*)d_out, b_top);
}

// round 7
// speedup vs baseline: 2.5964x; 1.0876x over previous
#include <cuda_runtime.h>

#define BB 16
#define NN 64
#define CC 32
#define NLVL 4
#define NB 60
#define NE 2048
#define NPAIR (BB*NN*NN)

// ---------------- device scratch (static; no allocs) ----------------
__device__ float g_a[2][BB*NN*CC];
__device__ float g_rep[4][BB*NN*7*CC];
__device__ float g_edge[4][NPAIR*CC];
__device__ float g_sph[NPAIR*16];
__device__ float2 g_fe[NPAIR];            // {frac, bitcast(e0)}
__device__ float g_part4[BB*NN*4];
__device__ float2 g_tab2[(NE+2)*512];     // {val[e], val[e+1]}, row NE+1 = zeros

// ---------------- rad*cut table, basis inline ----------------
__global__ void __launch_bounds__(256) k_table(const float* __restrict__ W_rad) {
    __shared__ float sW[NB*CC];
    __shared__ float sb[64*NB];
    int s   = blockIdx.y;
    int e0b = blockIdx.x * 64;
    int tid = threadIdx.x;
    const float* wr = W_rad + s*NB*CC;
    for (int idx = tid; idx < NB*CC; idx += 256) sW[idx] = wr[idx];
    for (int idx = tid; idx < 64*NB; idx += 256) {
        int row = idx / NB, k = idx - row*NB;
        float r = (float)(e0b + row) * (5.0f/NE);
        float d = r - (float)k * (5.0f/59.0f);
        sb[idx] = expf(-36.0f * d * d);
    }
    __syncthreads();
    int c = tid & 31, eg = tid >> 5;
    float acc[8];
    #pragma unroll
    for (int t = 0; t < 8; ++t) acc[t] = 0.0f;
    for (int k = 0; k < NB; ++k) {
        float wv = sW[k*CC + c];
        #pragma unroll
        for (int t = 0; t < 8; ++t)
            acc[t] = fmaf(sb[(eg*8 + t)*NB + k], wv, acc[t]);
    }
    #pragma unroll
    for (int t = 0; t < 8; ++t) {
        int e = e0b + eg*8 + t;
        if (e <= NE+1) {
            float r = (float)e * (5.0f/NE);
            float cut = 1.0f / (1.0f + __expf((r - 3.0f) * 2.0f));
            float v = (e <= NE) ? acc[t] * cut : 0.0f;   // row NE+1 = hard zero
            g_tab2[e*512 + s*32 + c].x = v;
            if (e > 0) g_tab2[(e-1)*512 + s*32 + c].y = v;
        }
    }
}

// ---------------- geometry + fused input featurization ----------------
__global__ void k_geom(const float* __restrict__ pos,
                       const float* __restrict__ oh, const int* __restrict__ charges,
                       const float* __restrict__ W_in, const float* __restrict__ b_in) {
    if (blockIdx.x >= 256) {   // fused a0 (BB*NN*CC = 32768 threads) + zero g_part4
        int t = (blockIdx.x - 256)*256 + threadIdx.x;   // 0..32767
        int c = t & 31, n = t >> 5;
        float ch = (float)charges[n] * (1.0f/9.0f);
        float p1 = ch, p2 = ch*ch;
        float acc = b_in[c];
        #pragma unroll
        for (int s = 0; s < 5; ++s) {
            float o = oh[n*5 + s];
            acc += o * (W_in[(s*3+0)*CC + c] + p1*W_in[(s*3+1)*CC + c] + p2*W_in[(s*3+2)*CC + c]);
        }
        g_a[0][t] = acc;
        g_rep[0][(n*7 + 0)*CC + c] = acc;
        if (t < BB*NN*4) g_part4[t] = 0.0f;
        return;
    }
    int t = blockIdx.x*256 + threadIdx.x;
    int b = t >> 12, i = (t >> 6) & 63, j = t & 63;
    const float* pi = pos + (b*NN+i)*3;
    const float* pj = pos + (b*NN+j)*3;
    float dx = pi[0]-pj[0], dy = pi[1]-pj[1], dz = pi[2]-pj[2];
    float r = sqrtf(dx*dx + dy*dy + dz*dz + 1e-12f);
    float inv = 1.0f / r;
    float x = dx*inv, y = dy*inv, z = dz*inv;

    bool masked = (i == j) || (r <= 1e-4f) || (r >= 5.0f);
    float fidx = r * ((float)NE / 5.0f);
    int e0 = (int)fidx;
    if (e0 > NE-1) e0 = NE-1;
    float fr = fidx - (float)e0;
    if (fr > 1.0f) fr = 1.0f;
    if (masked) { e0 = NE+1; fr = 0.0f; }
    g_fe[t] = make_float2(fr, __int_as_float(e0));

    float xx = x*x, yy = y*y, zz = z*z;
    float4 s0 = make_float4(1.0f, x, y, z);
    float4 s1 = make_float4(x*y, y*z, 3.0f*zz - 1.0f, x*z);
    float4 s2 = make_float4(xx - yy, y*(3.0f*xx - yy), x*y*z, y*(5.0f*zz - 1.0f));
    float4 s3 = make_float4(z*(5.0f*zz - 3.0f), x*(5.0f*zz - 1.0f),
                            z*(xx - yy), x*(xx - 3.0f*yy));
    float4* o = (float4*)(g_sph + t*16);
    o[0] = s0; o[1] = s1; o[2] = s2; o[3] = s3;
}

// ---------------- per-warp (atom, l) work ----------------
template<int L, bool HP>
__device__ __forceinline__ void atom_warp(
    const float* sa, const float* sWE, const float2* fe,
    float* sphw,                 // warp-private 512-float slice (sph + scratch)
    float* ge, const float2* tabbase, int i_local, int atom, int lane, int lvl, int s,
    const float* __restrict__ W_agg, const float* __restrict__ W_self,
    const float* __restrict__ W_top, float* anext)
{
    const int M = 2*L + 1;

    float vreg[32];
    #pragma unroll
    for (int d = 0; d < 32; ++d)
        vreg[d] = sa[i_local*CC + d] * sWE[d*CC + lane];

    float accm[M];
    #pragma unroll
    for (int m = 0; m < M; ++m) accm[m] = 0.0f;

    // depth-2 pipeline on table + previous-edge loads
    float2 fe0 = fe[0], fe1 = fe[1];
    float2 tv0 = tabbase[__float_as_int(fe0.y)*512];
    float2 tv1 = tabbase[__float_as_int(fe1.y)*512];
    float gp0 = HP ? ge[lane]      : 0.0f;
    float gp1 = HP ? ge[CC + lane] : 0.0f;

    #pragma unroll 4
    for (int jt = 0; jt < 64; ++jt) {
        float2 fen = make_float2(0.0f, 0.0f);
        float2 tvn = make_float2(0.0f, 0.0f);
        float  gpn = 0.0f;
        if (jt < 62) {
            fen = fe[jt + 2];
            tvn = tabbase[__float_as_int(fen.y)*512];
            if (HP) gpn = ge[(jt+2)*CC + lane];
        }
        const float4* aj4 = (const float4*)(sa + jt*CC);
        float ea0 = gp0, ea1 = 0.f, ea2 = 0.f, ea3 = 0.f;
        #pragma unroll
        for (int q = 0; q < 8; ++q) {
            float4 s4 = aj4[q];
            ea0 = fmaf(s4.x, vreg[4*q+0], ea0);
            ea1 = fmaf(s4.y, vreg[4*q+1], ea1);
            ea2 = fmaf(s4.z, vreg[4*q+2], ea2);
            ea3 = fmaf(s4.w, vreg[4*q+3], ea3);
        }
        float eacc = (ea0 + ea1) + (ea2 + ea3);
        float rad  = fmaf(fe0.x, tv0.y - tv0.x, tv0.x);
        float edge = rad * eacc;
        ge[jt*CC + lane] = edge;

        if (L == 0) {
            accm[0] += edge;
        } else {
            float4 A = *(const float4*)(sphw + jt*8);
            accm[0] = fmaf(edge, A.x, accm[0]);
            if (M > 1) accm[1] = fmaf(edge, A.y, accm[1]);
            if (M > 2) accm[2] = fmaf(edge, A.z, accm[2]);
            if (M > 3) accm[3] = fmaf(edge, A.w, accm[3]);
            if (M > 4) {
                float4 Bq = *(const float4*)(sphw + jt*8 + 4);
                accm[4] = fmaf(edge, Bq.x, accm[4]);
                if (M > 5) accm[5] = fmaf(edge, Bq.y, accm[5]);
                if (M > 6) accm[6] = fmaf(edge, Bq.z, accm[6]);
            }
        }
        fe0 = fe1; fe1 = fen;
        tv0 = tv1; tv1 = tvn;
        gp0 = gp1; gp1 = gpn;
    }

    // ---- per-warp epilogue (reuse warp's sph slice as scratch) ----
    __syncwarp();
    float* wmsg = sphw;
    float* sold = sphw + 256;
    bool has_self = (lvl > 0) || (L == 0);
    #pragma unroll
    for (int m = 0; m < M; ++m) {
        wmsg[m*32 + lane] = accm[m];
        sold[m*32 + lane] = has_self ? g_rep[L][(atom*7 + m)*CC + lane] : 0.0f;
    }
    __syncwarp();

    const float* wa  = W_agg  + s*CC*CC;
    const float* wsf = W_self + s*CC*CC;
    float f, s2 = 0.0f, rep0 = 0.0f;
    #pragma unroll
    for (int m = 0; m < M; ++m) {
        float r = 0.0f, r2 = 0.0f;
        #pragma unroll
        for (int c = 0; c < CC; ++c) {
            r  = fmaf(wmsg[m*32 + c], wa [c*CC + lane], r);
            r2 = fmaf(sold[m*32 + c], wsf[c*CC + lane], r2);
        }
        r += r2;
        g_rep[L][(atom*7 + m)*CC + lane] = r;
        if (m == 0) rep0 = r;
        s2 = fmaf(r, r, s2);
    }
    if (L == 0) {
        anext[atom*CC + lane] = rep0;
        f = rep0;
    } else {
        f = sqrtf(s2 + 1e-12f);
    }
    float part = f * W_top[s*CC + lane];
    #pragma unroll
    for (int off = 16; off; off >>= 1)
        part += __shfl_down_sync(0xffffffffu, part, off);
    if (lane == 0) g_part4[atom*4 + L] += part;
}

// ---------------- one (4-atom group, l) block; warp = one atom ----------------
__global__ void __launch_bounds__(128, 7) k_level(int lvl,
    const float* __restrict__ W_edge, const float* __restrict__ W_agg,
    const float* __restrict__ W_self, const float* __restrict__ W_top)
{
    __shared__ float  sa[NN*CC];        // 8 KB
    __shared__ float  sWE[CC*CC];       // 4 KB
    __shared__ float2 sfe[4*NN];        // 2 KB
    __shared__ float  ssph[4*NN*8];     // 8 KB; warp slices, reused in epilogue

    const float* acur  = g_a[lvl & 1];
    float*       anext = g_a[(lvl + 1) & 1];

    int blk = blockIdx.x;
    int l  = blk & 3;
    int g4 = blk >> 2;                 // group of 4 atoms, 0..255
    int b  = g4 >> 4;
    const int M = 2*l + 1;
    int tid = threadIdx.x, w = tid >> 5, lane = tid & 31;
    int atom0 = g4*4;
    int s = lvl*4 + l;

    for (int idx = tid; idx < NN*CC/4; idx += 128)
        ((float4*)sa)[idx] = ((const float4*)(acur + b*NN*CC))[idx];
    {
        const float4* wsrc = (const float4*)(W_edge + s*CC*CC);
        for (int idx = tid; idx < CC*CC/4; idx += 128)
            ((float4*)sWE)[idx] = wsrc[idx];
    }
    for (int t = tid; t < 4*NN; t += 128)
        sfe[t] = g_fe[atom0*NN + t];
    if (l > 0) {
        for (int t = tid; t < 4*NN*8; t += 128) {
            int wi = t >> 9, rem = t & 511, j = rem >> 3, m = rem & 7;
            ssph[t] = (m < M) ? g_sph[((atom0 + wi)*NN + j)*16 + l*l + m] : 0.0f;
        }
    }
    __syncthreads();

    int atom = atom0 + w;
    int i_local = atom & 63;
    float* ge = g_edge[l] + atom*NN*CC;
    const float2* tabbase = g_tab2 + s*32 + lane;
    const float2* fe = sfe + w*NN;
    float* sphw = ssph + w*512;

    if (lvl == 0) {
        switch (l) {
            case 0: atom_warp<0,false>(sa,sWE,fe,sphw,ge,tabbase,i_local,atom,lane,lvl,s,W_agg,W_self,W_top,anext); break;
            case 1: atom_warp<1,false>(sa,sWE,fe,sphw,ge,tabbase,i_local,atom,lane,lvl,s,W_agg,W_self,W_top,anext); break;
            case 2: atom_warp<2,false>(sa,sWE,fe,sphw,ge,tabbase,i_local,atom,lane,lvl,s,W_agg,W_self,W_top,anext); break;
            default:atom_warp<3,false>(sa,sWE,fe,sphw,ge,tabbase,i_local,atom,lane,lvl,s,W_agg,W_self,W_top,anext); break;
        }
    } else {
        switch (l) {
            case 0: atom_warp<0,true >(sa,sWE,fe,sphw,ge,tabbase,i_local,atom,lane,lvl,s,W_agg,W_self,W_top,anext); break;
            case 1: atom_warp<1,true >(sa,sWE,fe,sphw,ge,tabbase,i_local,atom,lane,lvl,s,W_agg,W_self,W_top,anext); break;
            case 2: atom_warp<2,true >(sa,sWE,fe,sphw,ge,tabbase,i_local,atom,lane,lvl,s,W_agg,W_self,W_top,anext); break;
            default:atom_warp<3,true >(sa,sWE,fe,sphw,ge,tabbase,i_local,atom,lane,lvl,s,W_agg,W_self,W_top,anext); break;
        }
    }
}

// ---------------- output ----------------
__global__ void k_out(float* __restrict__ out, const float* __restrict__ b_top) {
    __shared__ float sh[256];
    int b = blockIdx.x, t = threadIdx.x;
    sh[t] = g_part4[b*256 + t];
    __syncthreads();
    #pragma unroll
    for (int off = 128; off; off >>= 1) {
        if (t < off) sh[t] += sh[t + off];
        __syncthreads();
    }
    if (t == 0) out[b] = sh[0] + b_top[0];
}

// ---------------- launch ----------------
extern "C" void kernel_launch(void* const* d_in, const int* in_sizes, int n_in,
                              void* d_out, int out_size) {
    const float* pos     = (const float*)d_in[0];
    const float* oh      = (const float*)d_in[1];
    const int*   charges = (const int*)  d_in[2];
    const float* W_in    = (const float*)d_in[5];
    const float* b_in    = (const float*)d_in[6];
    const float* W_rad   = (const float*)d_in[7];
    const float* W_edge  = (const float*)d_in[8];
    const float* W_agg   = (const float*)d_in[9];
    const float* W_self  = (const float*)d_in[10];
    const float* W_top   = (const float*)d_in[11];
    const float* b_top   = (const float*)d_in[12];

    k_table<<<dim3(33, 16), 256>>>(W_rad);
    k_geom<<<256 + 128, 256>>>(pos, oh, charges, W_in, b_in);   // 256 geom + 128 a0 blocks
    for (int lvl = 0; lvl < NLVL; ++lvl)
        k_level<<<BB*NN, 128>>>(lvl, W_edge, W_agg, W_self, W_top);
    k_out<<<BB, 256>>>((float*)d_out, b_top);
}